// round 9
// baseline (speedup 1.0000x reference)
#include <cuda_runtime.h>
#include <cuda_fp16.h>
#include <cstdint>

#define NN 100000
#define NE 1600000
#define D  128
#define NPAD (NN + 128)

typedef unsigned int u32;
typedef unsigned long long u64;

// ---- scratch (static device globals; allocation-free) ----
__device__ int    g_rowptr[NN + 1];
__device__ int    g_cursor[NN];
__device__ int    g_col[NE];
__device__ u64    g_bstate[128];
__device__ __align__(16) __half g_hh[(size_t)NPAD * D];   // h (fp16)
__device__ __align__(16) __half g_yl[(size_t)NPAD * D];   // A@W_l (fp16)
__device__ __align__(16) __half g_z [(size_t)NPAD * D];   // A@W_r + b (fp16)
__device__ __align__(16) u32 g_B[4][64 * 128];            // fp16 weights k-pair packed

// ---------------- helpers ----------------
__device__ __forceinline__ u32 pack2(__half a, __half b) {
    __half2 h = __halves2half2(a, b);
    return *(u32*)&h;
}
__device__ __forceinline__ void mma16816(float* c, const u32* a, const u32* b) {
    asm volatile(
        "mma.sync.aligned.m16n8k16.row.col.f32.f16.f16.f32 "
        "{%0,%1,%2,%3}, {%4,%5,%6,%7}, {%8,%9}, {%0,%1,%2,%3};"
        : "+f"(c[0]), "+f"(c[1]), "+f"(c[2]), "+f"(c[3])
        : "r"(a[0]), "r"(a[1]), "r"(a[2]), "r"(a[3]), "r"(b[0]), "r"(b[1]));
}

// ---------------- CSR build ----------------
__global__ void k_zero(int n) {
    int i = blockIdx.x * blockDim.x + threadIdx.x;
    if (i < 128) g_bstate[i] = 0ULL;
    if (i < n) g_cursor[i] = 0;
}
__global__ void k_hist(const int* __restrict__ dst, int e4) {
    int i = blockIdx.x * blockDim.x + threadIdx.x;
    if (i >= e4) return;
    int4 d = ((const int4*)dst)[i];
    atomicAdd(&g_cursor[d.x], 1);
    atomicAdd(&g_cursor[d.y], 1);
    atomicAdd(&g_cursor[d.z], 1);
    atomicAdd(&g_cursor[d.w], 1);
}
// single-pass decoupled-lookback scan: counts -> rowptr/cursor (exclusive)
__global__ void k_scanLB(int n, int e) {
    __shared__ int sh[1024];
    __shared__ int s_T;
    __shared__ int s_prefix;
    int bid = blockIdx.x, t = threadIdx.x;
    int i = bid * 1024 + t;
    int v = (i < n) ? g_cursor[i] : 0;
    sh[t] = v;
    __syncthreads();
    for (int off = 1; off < 1024; off <<= 1) {
        int w = (t >= off) ? sh[t - off] : 0;
        __syncthreads();
        sh[t] += w;
        __syncthreads();
    }
    if (t == 1023) s_T = sh[1023];
    if (t == 0 && bid == 0) s_prefix = 0;
    __syncthreads();
    int T = s_T;

    if (t == 0) {
        u64 st = ((u64)(unsigned)T << 32) | (bid == 0 ? 2ULL : 1ULL);
        atomicExch(&g_bstate[bid], st);
    }
    if (t < 32 && bid > 0) {
        int lane = t;
        int prefix = 0;
        int base = bid - 1;
        while (true) {
            int j = base - lane;
            u64 s = (j >= 0) ? *(volatile u64*)&g_bstate[j] : 2ULL;
            unsigned f = (unsigned)(s & 3ULL);
            if (__all_sync(0xFFFFFFFFu, f != 0u)) {
                int val = (int)(unsigned)(s >> 32);
                unsigned pm = __ballot_sync(0xFFFFFFFFu, f == 2u);
                if (pm) {
                    int fp = __ffs(pm) - 1;
                    int xx = (lane <= fp) ? val : 0;
                    #pragma unroll
                    for (int o = 16; o; o >>= 1) xx += __shfl_xor_sync(0xFFFFFFFFu, xx, o);
                    prefix += xx;
                    break;
                } else {
                    int xx = val;
                    #pragma unroll
                    for (int o = 16; o; o >>= 1) xx += __shfl_xor_sync(0xFFFFFFFFu, xx, o);
                    prefix += xx;
                    base -= 32;
                }
            }
        }
        if (lane == 0) {
            atomicExch(&g_bstate[bid], ((u64)(unsigned)(prefix + T) << 32) | 2ULL);
            s_prefix = prefix;
        }
    }
    __syncthreads();
    int r = s_prefix + sh[t] - v;
    if (i < n) {
        g_rowptr[i] = r;
        g_cursor[i] = r;
    }
    if (bid == 0 && t == 0) g_rowptr[n] = e;
}
__global__ void k_scatter(const int* __restrict__ src, const int* __restrict__ dst, int e4) {
    int i = blockIdx.x * blockDim.x + threadIdx.x;
    if (i >= e4) return;
    int4 s = ((const int4*)src)[i];
    int4 d = ((const int4*)dst)[i];
    int p0 = atomicAdd(&g_cursor[d.x], 1); g_col[p0] = s.x;
    int p1 = atomicAdd(&g_cursor[d.y], 1); g_col[p1] = s.y;
    int p2 = atomicAdd(&g_cursor[d.z], 1); g_col[p2] = s.z;
    int p3 = atomicAdd(&g_cursor[d.w], 1); g_col[p3] = s.w;
}

// ---------------- weight prep: fp32 W[k][n] -> fp16 k-pair-packed [kp][n] ----------------
__global__ void k_prepB(const float* __restrict__ W0, const float* __restrict__ W1,
                        const float* __restrict__ W2, const float* __restrict__ W3) {
    const float* Ws[4] = {W0, W1, W2, W3};
    const float* W = Ws[blockIdx.x];
    u32* b = g_B[blockIdx.x];
    for (int u = threadIdx.x; u < 64 * 128; u += blockDim.x) {
        int kp = u >> 7, n = u & 127;
        b[u] = pack2(__float2half_rn(W[(2 * kp) * D + n]),
                     __float2half_rn(W[(2 * kp + 1) * D + n]));
    }
}

// ---------------- HMMA cat-GEMM: [yl | z] = A @ [Bl | Br] (+bias on z) ----------------
#define AS 68
#define BS 264
#define SM_U32_TOTAL (128 * AS + 64 * BS)

__global__ __launch_bounds__(256, 1) void k_gemm(
    const float* __restrict__ A32, const __half* __restrict__ A16, int a32,
    const u32* __restrict__ Bg0, const u32* __restrict__ Bg1,
    const float* __restrict__ bias,
    __half* __restrict__ yl, __half* __restrict__ z, int M)
{
    extern __shared__ __align__(16) u32 sm[];
    u32* Asm = sm;
    u32* Bsm = sm + 128 * AS;

    int tid = threadIdx.x, wid = tid >> 5, lane = tid & 31;
    int g = lane >> 2, tg = lane & 3;
    int wm = (wid & 1) * 64, wn = (wid >> 1) * 64;
    int m0 = blockIdx.x * 128;

    for (int u = tid; u < 2048; u += 256) {
        int r = u >> 5, c4 = u & 31;
        *(uint4*)&Bsm[r * BS + c4 * 4]       = ((const uint4*)Bg0)[u];
        *(uint4*)&Bsm[r * BS + 128 + c4 * 4] = ((const uint4*)Bg1)[u];
    }
    if (a32) {
        for (int u = tid; u < 2048; u += 256) {
            int r = u >> 4, c4 = u & 15;
            int gr = m0 + r;
            float4 fa = make_float4(0.f, 0.f, 0.f, 0.f), fb = fa;
            if (gr < M) {
                const float4* p = (const float4*)(A32 + (size_t)gr * D + c4 * 8);
                fa = p[0]; fb = p[1];
            }
            *(uint4*)&Asm[r * AS + c4 * 4] = make_uint4(
                pack2(__float2half_rn(fa.x), __float2half_rn(fa.y)),
                pack2(__float2half_rn(fa.z), __float2half_rn(fa.w)),
                pack2(__float2half_rn(fb.x), __float2half_rn(fb.y)),
                pack2(__float2half_rn(fb.z), __float2half_rn(fb.w)));
        }
    } else {
        const u32* Ag = (const u32*)A16;
        for (int u = tid; u < 2048; u += 256) {
            int r = u >> 4, c4 = u & 15;
            *(uint4*)&Asm[r * AS + c4 * 4] =
                *(const uint4*)(Ag + (size_t)(m0 + r) * 64 + c4 * 4);
        }
    }
    __syncthreads();

    float acc[4][8][4];
    #pragma unroll
    for (int mt = 0; mt < 4; ++mt)
        #pragma unroll
        for (int nt = 0; nt < 8; ++nt)
            #pragma unroll
            for (int c = 0; c < 4; ++c) acc[mt][nt][c] = 0.f;

    #pragma unroll
    for (int ks = 0; ks < 8; ++ks) {
        u32 afr[4][4];
        #pragma unroll
        for (int mt = 0; mt < 4; ++mt) {
            int r = wm + mt * 16 + g;
            afr[mt][0] = Asm[r * AS + ks * 8 + tg];
            afr[mt][1] = Asm[(r + 8) * AS + ks * 8 + tg];
            afr[mt][2] = Asm[r * AS + ks * 8 + tg + 4];
            afr[mt][3] = Asm[(r + 8) * AS + ks * 8 + tg + 4];
        }
        u32 bfr[8][2];
        #pragma unroll
        for (int nt = 0; nt < 8; ++nt) {
            int n = wn + nt * 8 + g;
            bfr[nt][0] = Bsm[(ks * 8 + tg) * BS + n];
            bfr[nt][1] = Bsm[(ks * 8 + tg + 4) * BS + n];
        }
        #pragma unroll
        for (int mt = 0; mt < 4; ++mt)
            #pragma unroll
            for (int nt = 0; nt < 8; ++nt)
                mma16816(acc[mt][nt], afr[mt], bfr[nt]);
    }

    #pragma unroll
    for (int nt = 0; nt < 8; ++nt) {
        int ccol = wn + nt * 8 + tg * 2;
        if (ccol < 128) {
            #pragma unroll
            for (int mt = 0; mt < 4; ++mt) {
                int r0 = m0 + wm + mt * 16 + g;
                *(__half2*)(yl + (size_t)r0 * D + ccol) =
                    __floats2half2_rn(acc[mt][nt][0], acc[mt][nt][1]);
                *(__half2*)(yl + (size_t)(r0 + 8) * D + ccol) =
                    __floats2half2_rn(acc[mt][nt][2], acc[mt][nt][3]);
            }
        } else {
            int zc = ccol - 128;
            float bv0 = __ldg(bias + zc), bv1 = __ldg(bias + zc + 1);
            #pragma unroll
            for (int mt = 0; mt < 4; ++mt) {
                int r0 = m0 + wm + mt * 16 + g;
                *(__half2*)(z + (size_t)r0 * D + zc) =
                    __floats2half2_rn(acc[mt][nt][0] + bv0, acc[mt][nt][1] + bv1);
                *(__half2*)(z + (size_t)(r0 + 8) * D + zc) =
                    __floats2half2_rn(acc[mt][nt][2] + bv0, acc[mt][nt][3] + bv1);
            }
        }
    }
}

// ---------------- fused mean-agg + add-self + (relu) ----------------
// warp per node; col indices loaded once per 32 edges + shfl-broadcast;
// feature gathers batched 16/8/1 for deep MLP with no pointer-chase.
#define ACC8(U) do { \
    float2 _f0 = __half22float2(*(__half2*)&(U).x); \
    float2 _f1 = __half22float2(*(__half2*)&(U).y); \
    a0 += _f0.x; a1 += _f0.y; a2 += _f1.x; a3 += _f1.y; } while (0)

__global__ void k_aggf(const __half* __restrict__ yl, const __half* __restrict__ z,
                       __half* __restrict__ outh, float* __restrict__ outf,
                       int relu, int n)
{
    const unsigned FULL = 0xFFFFFFFFu;
    int w    = (blockIdx.x * blockDim.x + threadIdx.x) >> 5;
    int lane = threadIdx.x & 31;
    if (w >= n) return;
    int beg = g_rowptr[w], end = g_rowptr[w + 1];
    float a0 = 0.f, a1 = 0.f, a2 = 0.f, a3 = 0.f;

    for (int b = beg; b < end; b += 32) {
        int cnt = end - b;
        if (cnt > 32) cnt = 32;
        int cv = (lane < cnt) ? g_col[b + lane] : 0;
        int q = 0;
        for (; q + 16 <= cnt; q += 16) {
            uint2 u[16];
            #pragma unroll
            for (int t = 0; t < 16; ++t) {
                int s = __shfl_sync(FULL, cv, q + t);
                u[t] = *((const uint2*)(yl + (size_t)s * D) + lane);
            }
            #pragma unroll
            for (int t = 0; t < 16; ++t) ACC8(u[t]);
        }
        if (q + 8 <= cnt) {
            uint2 u[8];
            #pragma unroll
            for (int t = 0; t < 8; ++t) {
                int s = __shfl_sync(FULL, cv, q + t);
                u[t] = *((const uint2*)(yl + (size_t)s * D) + lane);
            }
            #pragma unroll
            for (int t = 0; t < 8; ++t) ACC8(u[t]);
            q += 8;
        }
        for (; q < cnt; ++q) {
            int s = __shfl_sync(FULL, cv, q);
            uint2 u = *((const uint2*)(yl + (size_t)s * D) + lane);
            ACC8(u);
        }
    }

    int deg = end - beg;
    float inv = 1.0f / (float)(deg > 1 ? deg : 1);
    uint2 zu = *((const uint2*)(z + (size_t)w * D) + lane);
    float2 z0 = __half22float2(*(__half2*)&zu.x);
    float2 z1 = __half22float2(*(__half2*)&zu.y);
    float v0 = a0 * inv + z0.x, v1 = a1 * inv + z0.y;
    float v2 = a2 * inv + z1.x, v3 = a3 * inv + z1.y;
    if (relu) {
        v0 = v0 > 0.f ? v0 : 0.f; v1 = v1 > 0.f ? v1 : 0.f;
        v2 = v2 > 0.f ? v2 : 0.f; v3 = v3 > 0.f ? v3 : 0.f;
    }
    if (outh) {
        *((uint2*)(outh + (size_t)w * D) + lane) =
            make_uint2(pack2(__float2half_rn(v0), __float2half_rn(v1)),
                       pack2(__float2half_rn(v2), __float2half_rn(v3)));
    } else {
        *((float4*)(outf + (size_t)w * D) + lane) = make_float4(v0, v1, v2, v3);
    }
}

// ---------------- launch ----------------
extern "C" void kernel_launch(void* const* d_in, const int* in_sizes, int n_in,
                              void* d_out, int out_size)
{
    const float* x   = (const float*)d_in[0];
    const int*   ei  = (const int*)d_in[1];
    const float* W1l = (const float*)d_in[2];
    const float* b1  = (const float*)d_in[3];
    const float* W1r = (const float*)d_in[4];
    const float* W2l = (const float*)d_in[5];
    const float* b2  = (const float*)d_in[6];
    const float* W2r = (const float*)d_in[7];
    float* out = (float*)d_out;

    int N = in_sizes[0] / D;
    int E = in_sizes[1] / 2;
    const int* src = ei;
    const int* dst = ei + E;

    __half *hh, *yl, *z;
    u32 *B0, *B1, *B2, *B3;
    cudaGetSymbolAddress((void**)&hh, g_hh);
    cudaGetSymbolAddress((void**)&yl, g_yl);
    cudaGetSymbolAddress((void**)&z,  g_z);
    {
        u32* bb;
        cudaGetSymbolAddress((void**)&bb, g_B);
        B0 = bb; B1 = bb + 8192; B2 = bb + 16384; B3 = bb + 24576;
    }

    cudaFuncSetAttribute(k_gemm, cudaFuncAttributeMaxDynamicSharedMemorySize,
                         SM_U32_TOTAL * 4);

    static cudaStream_t sB = nullptr;
    static cudaEvent_t evFork = nullptr, evJoin = nullptr;
    if (!sB) {
        cudaStreamCreateWithFlags(&sB, cudaStreamNonBlocking);
        cudaEventCreateWithFlags(&evFork, cudaEventDisableTiming);
        cudaEventCreateWithFlags(&evJoin, cudaEventDisableTiming);
    }

    int e4 = (E + 3) / 4;
    int nb = (N + 1023) / 1024;
    int aggBlocks  = (N * 32 + 255) / 256;
    int gemmBlocks = (N + 127) / 128;

    // fork: CSR build on side stream
    cudaEventRecord(evFork, 0);
    cudaStreamWaitEvent(sB, evFork, 0);
    k_zero   <<<(N + 255) / 256, 256, 0, sB>>>(N);
    k_hist   <<<(e4 + 255) / 256, 256, 0, sB>>>(dst, e4);
    k_scanLB <<<nb, 1024, 0, sB>>>(N, E);
    k_scatter<<<(e4 + 255) / 256, 256, 0, sB>>>(src, dst, e4);
    cudaEventRecord(evJoin, sB);

    // main stream: weights + layer-1 GEMM (reads fp32 x directly)
    k_prepB<<<4, 256>>>(W1l, W1r, W2l, W2r);
    k_gemm <<<gemmBlocks, 256, SM_U32_TOTAL * 4>>>(
        x, nullptr, 1, B0, B1, b1, yl, z, N);

    // join, then agg/gemm/agg
    cudaStreamWaitEvent(0, evJoin, 0);
    k_aggf<<<aggBlocks, 256>>>(yl, z, hh, nullptr, 1, N);
    k_gemm<<<gemmBlocks, 256, SM_U32_TOTAL * 4>>>(
        nullptr, hh, 0, B2, B3, b2, yl, z, N);
    k_aggf<<<aggBlocks, 256>>>(yl, z, nullptr, out, 0, N);
}

// round 10
// speedup vs baseline: 1.2118x; 1.2118x over previous
#include <cuda_runtime.h>
#include <cuda_fp16.h>
#include <cstdint>

#define NN 100000
#define NE 1600000
#define D  128
#define NPAD (NN + 128)

typedef unsigned int u32;
typedef unsigned long long u64;

// ---- scratch (static device globals; allocation-free) ----
__device__ int    g_rowptr[NN + 1];
__device__ int    g_cursor[NN];
__device__ int    g_col[NE];
__device__ u64    g_bstate[128];
__device__ __align__(16) __half g_hh[(size_t)NPAD * D];   // h (fp16)
__device__ __align__(16) __half g_yl[(size_t)NPAD * D];   // A@W_l (fp16)
__device__ __align__(16) __half g_z [(size_t)NPAD * D];   // A@W_r + b (fp16)
__device__ __align__(16) u32 g_B[4][64 * 128];            // fp16 weights k-pair packed

// ---------------- helpers ----------------
__device__ __forceinline__ u32 pack2(__half a, __half b) {
    __half2 h = __halves2half2(a, b);
    return *(u32*)&h;
}
__device__ __forceinline__ void mma16816(float* c, const u32* a, const u32* b) {
    asm volatile(
        "mma.sync.aligned.m16n8k16.row.col.f32.f16.f16.f32 "
        "{%0,%1,%2,%3}, {%4,%5,%6,%7}, {%8,%9}, {%0,%1,%2,%3};"
        : "+f"(c[0]), "+f"(c[1]), "+f"(c[2]), "+f"(c[3])
        : "r"(a[0]), "r"(a[1]), "r"(a[2]), "r"(a[3]), "r"(b[0]), "r"(b[1]));
}

// ---------------- CSR build ----------------
__global__ void k_zero(int n) {
    int i = blockIdx.x * blockDim.x + threadIdx.x;
    if (i < 128) g_bstate[i] = 0ULL;
    if (i < n) g_cursor[i] = 0;
}
__global__ void k_hist(const int* __restrict__ dst, int e4) {
    int i = blockIdx.x * blockDim.x + threadIdx.x;
    if (i >= e4) return;
    int4 d = ((const int4*)dst)[i];
    atomicAdd(&g_cursor[d.x], 1);
    atomicAdd(&g_cursor[d.y], 1);
    atomicAdd(&g_cursor[d.z], 1);
    atomicAdd(&g_cursor[d.w], 1);
}
// single-pass decoupled-lookback scan: counts -> rowptr/cursor (exclusive)
__global__ void k_scanLB(int n, int e) {
    __shared__ int sh[1024];
    __shared__ int s_T;
    __shared__ int s_prefix;
    int bid = blockIdx.x, t = threadIdx.x;
    int i = bid * 1024 + t;
    int v = (i < n) ? g_cursor[i] : 0;
    sh[t] = v;
    __syncthreads();
    for (int off = 1; off < 1024; off <<= 1) {
        int w = (t >= off) ? sh[t - off] : 0;
        __syncthreads();
        sh[t] += w;
        __syncthreads();
    }
    if (t == 1023) s_T = sh[1023];
    if (t == 0 && bid == 0) s_prefix = 0;
    __syncthreads();
    int T = s_T;

    if (t == 0) {
        u64 st = ((u64)(unsigned)T << 32) | (bid == 0 ? 2ULL : 1ULL);
        atomicExch(&g_bstate[bid], st);
    }
    if (t < 32 && bid > 0) {
        int lane = t;
        int prefix = 0;
        int base = bid - 1;
        while (true) {
            int j = base - lane;
            u64 s = (j >= 0) ? *(volatile u64*)&g_bstate[j] : 2ULL;
            unsigned f = (unsigned)(s & 3ULL);
            if (__all_sync(0xFFFFFFFFu, f != 0u)) {
                int val = (int)(unsigned)(s >> 32);
                unsigned pm = __ballot_sync(0xFFFFFFFFu, f == 2u);
                if (pm) {
                    int fp = __ffs(pm) - 1;
                    int xx = (lane <= fp) ? val : 0;
                    #pragma unroll
                    for (int o = 16; o; o >>= 1) xx += __shfl_xor_sync(0xFFFFFFFFu, xx, o);
                    prefix += xx;
                    break;
                } else {
                    int xx = val;
                    #pragma unroll
                    for (int o = 16; o; o >>= 1) xx += __shfl_xor_sync(0xFFFFFFFFu, xx, o);
                    prefix += xx;
                    base -= 32;
                }
            }
        }
        if (lane == 0) {
            atomicExch(&g_bstate[bid], ((u64)(unsigned)(prefix + T) << 32) | 2ULL);
            s_prefix = prefix;
        }
    }
    __syncthreads();
    int r = s_prefix + sh[t] - v;
    if (i < n) {
        g_rowptr[i] = r;
        g_cursor[i] = r;
    }
    if (bid == 0 && t == 0) g_rowptr[n] = e;
}
__global__ void k_scatter(const int* __restrict__ src, const int* __restrict__ dst, int e4) {
    int i = blockIdx.x * blockDim.x + threadIdx.x;
    if (i >= e4) return;
    int4 s = ((const int4*)src)[i];
    int4 d = ((const int4*)dst)[i];
    int p0 = atomicAdd(&g_cursor[d.x], 1); g_col[p0] = s.x;
    int p1 = atomicAdd(&g_cursor[d.y], 1); g_col[p1] = s.y;
    int p2 = atomicAdd(&g_cursor[d.z], 1); g_col[p2] = s.z;
    int p3 = atomicAdd(&g_cursor[d.w], 1); g_col[p3] = s.w;
}

// ---------------- weight prep: fp32 W[k][n] -> fp16 k-pair-packed [kp][n] ----------------
__global__ void k_prepB(const float* __restrict__ W0, const float* __restrict__ W1,
                        const float* __restrict__ W2, const float* __restrict__ W3) {
    const float* Ws[4] = {W0, W1, W2, W3};
    const float* W = Ws[blockIdx.x];
    u32* b = g_B[blockIdx.x];
    for (int u = threadIdx.x; u < 64 * 128; u += blockDim.x) {
        int kp = u >> 7, n = u & 127;
        b[u] = pack2(__float2half_rn(W[(2 * kp) * D + n]),
                     __float2half_rn(W[(2 * kp + 1) * D + n]));
    }
}

// ---------------- HMMA cat-GEMM: [yl | z] = A @ [Bl | Br] (+bias on z) ----------------
#define AS 68
#define BS 264
#define SM_U32_TOTAL (128 * AS + 64 * BS)

__global__ __launch_bounds__(256, 1) void k_gemm(
    const float* __restrict__ A32, const __half* __restrict__ A16, int a32,
    const u32* __restrict__ Bg0, const u32* __restrict__ Bg1,
    const float* __restrict__ bias,
    __half* __restrict__ yl, __half* __restrict__ z, int M)
{
    extern __shared__ __align__(16) u32 sm[];
    u32* Asm = sm;
    u32* Bsm = sm + 128 * AS;

    int tid = threadIdx.x, wid = tid >> 5, lane = tid & 31;
    int g = lane >> 2, tg = lane & 3;
    int wm = (wid & 1) * 64, wn = (wid >> 1) * 64;
    int m0 = blockIdx.x * 128;

    for (int u = tid; u < 2048; u += 256) {
        int r = u >> 5, c4 = u & 31;
        *(uint4*)&Bsm[r * BS + c4 * 4]       = ((const uint4*)Bg0)[u];
        *(uint4*)&Bsm[r * BS + 128 + c4 * 4] = ((const uint4*)Bg1)[u];
    }
    if (a32) {
        for (int u = tid; u < 2048; u += 256) {
            int r = u >> 4, c4 = u & 15;
            int gr = m0 + r;
            float4 fa = make_float4(0.f, 0.f, 0.f, 0.f), fb = fa;
            if (gr < M) {
                const float4* p = (const float4*)(A32 + (size_t)gr * D + c4 * 8);
                fa = p[0]; fb = p[1];
            }
            *(uint4*)&Asm[r * AS + c4 * 4] = make_uint4(
                pack2(__float2half_rn(fa.x), __float2half_rn(fa.y)),
                pack2(__float2half_rn(fa.z), __float2half_rn(fa.w)),
                pack2(__float2half_rn(fb.x), __float2half_rn(fb.y)),
                pack2(__float2half_rn(fb.z), __float2half_rn(fb.w)));
        }
    } else {
        const u32* Ag = (const u32*)A16;
        for (int u = tid; u < 2048; u += 256) {
            int r = u >> 4, c4 = u & 15;
            *(uint4*)&Asm[r * AS + c4 * 4] =
                *(const uint4*)(Ag + (size_t)(m0 + r) * 64 + c4 * 4);
        }
    }
    __syncthreads();

    float acc[4][8][4];
    #pragma unroll
    for (int mt = 0; mt < 4; ++mt)
        #pragma unroll
        for (int nt = 0; nt < 8; ++nt)
            #pragma unroll
            for (int c = 0; c < 4; ++c) acc[mt][nt][c] = 0.f;

    #pragma unroll
    for (int ks = 0; ks < 8; ++ks) {
        u32 afr[4][4];
        #pragma unroll
        for (int mt = 0; mt < 4; ++mt) {
            int r = wm + mt * 16 + g;
            afr[mt][0] = Asm[r * AS + ks * 8 + tg];
            afr[mt][1] = Asm[(r + 8) * AS + ks * 8 + tg];
            afr[mt][2] = Asm[r * AS + ks * 8 + tg + 4];
            afr[mt][3] = Asm[(r + 8) * AS + ks * 8 + tg + 4];
        }
        u32 bfr[8][2];
        #pragma unroll
        for (int nt = 0; nt < 8; ++nt) {
            int n = wn + nt * 8 + g;
            bfr[nt][0] = Bsm[(ks * 8 + tg) * BS + n];
            bfr[nt][1] = Bsm[(ks * 8 + tg + 4) * BS + n];
        }
        #pragma unroll
        for (int mt = 0; mt < 4; ++mt)
            #pragma unroll
            for (int nt = 0; nt < 8; ++nt)
                mma16816(acc[mt][nt], afr[mt], bfr[nt]);
    }

    #pragma unroll
    for (int nt = 0; nt < 8; ++nt) {
        int ccol = wn + nt * 8 + tg * 2;
        if (ccol < 128) {
            #pragma unroll
            for (int mt = 0; mt < 4; ++mt) {
                int r0 = m0 + wm + mt * 16 + g;
                *(__half2*)(yl + (size_t)r0 * D + ccol) =
                    __floats2half2_rn(acc[mt][nt][0], acc[mt][nt][1]);
                *(__half2*)(yl + (size_t)(r0 + 8) * D + ccol) =
                    __floats2half2_rn(acc[mt][nt][2], acc[mt][nt][3]);
            }
        } else {
            int zc = ccol - 128;
            float bv0 = __ldg(bias + zc), bv1 = __ldg(bias + zc + 1);
            #pragma unroll
            for (int mt = 0; mt < 4; ++mt) {
                int r0 = m0 + wm + mt * 16 + g;
                *(__half2*)(z + (size_t)r0 * D + zc) =
                    __floats2half2_rn(acc[mt][nt][0] + bv0, acc[mt][nt][1] + bv1);
                *(__half2*)(z + (size_t)(r0 + 8) * D + zc) =
                    __floats2half2_rn(acc[mt][nt][2] + bv0, acc[mt][nt][3] + bv1);
            }
        }
    }
}

// ---------------- fused mean-agg + add-self + (relu) ----------------
// R8 loop (8-deep direct-index batches) + next-batch col prefetch.
__global__ void k_aggf(const __half* __restrict__ yl, const __half* __restrict__ z,
                       __half* __restrict__ outh, float* __restrict__ outf,
                       int relu, int n)
{
    int w    = (blockIdx.x * blockDim.x + threadIdx.x) >> 5;
    int lane = threadIdx.x & 31;
    if (w >= n) return;
    int beg = g_rowptr[w], end = g_rowptr[w + 1];
    float a0 = 0.f, a1 = 0.f, a2 = 0.f, a3 = 0.f;
    int j = beg;

    if (j + 8 <= end) {
        int c[8];
        #pragma unroll
        for (int q = 0; q < 8; ++q) c[q] = g_col[j + q];
        while (true) {
            uint2 u[8];
            #pragma unroll
            for (int q = 0; q < 8; ++q)
                u[q] = *((const uint2*)(yl + (size_t)c[q] * D) + lane);
            int jn = j + 8;
            bool more = (jn + 8 <= end);
            if (more) {
                #pragma unroll
                for (int q = 0; q < 8; ++q) c[q] = g_col[jn + q];   // prefetch next cols
            }
            #pragma unroll
            for (int q = 0; q < 8; ++q) {
                float2 f0 = __half22float2(*(__half2*)&u[q].x);
                float2 f1 = __half22float2(*(__half2*)&u[q].y);
                a0 += f0.x; a1 += f0.y; a2 += f1.x; a3 += f1.y;
            }
            j = jn;
            if (!more) break;
        }
    }
    for (; j < end; ++j) {
        int s = g_col[j];
        uint2 u = *((const uint2*)(yl + (size_t)s * D) + lane);
        float2 f0 = __half22float2(*(__half2*)&u.x);
        float2 f1 = __half22float2(*(__half2*)&u.y);
        a0 += f0.x; a1 += f0.y; a2 += f1.x; a3 += f1.y;
    }

    int deg = end - beg;
    float inv = 1.0f / (float)(deg > 1 ? deg : 1);
    uint2 zu = *((const uint2*)(z + (size_t)w * D) + lane);
    float2 z0 = __half22float2(*(__half2*)&zu.x);
    float2 z1 = __half22float2(*(__half2*)&zu.y);
    float v0 = a0 * inv + z0.x, v1 = a1 * inv + z0.y;
    float v2 = a2 * inv + z1.x, v3 = a3 * inv + z1.y;
    if (relu) {
        v0 = v0 > 0.f ? v0 : 0.f; v1 = v1 > 0.f ? v1 : 0.f;
        v2 = v2 > 0.f ? v2 : 0.f; v3 = v3 > 0.f ? v3 : 0.f;
    }
    if (outh) {
        *((uint2*)(outh + (size_t)w * D) + lane) =
            make_uint2(pack2(__float2half_rn(v0), __float2half_rn(v1)),
                       pack2(__float2half_rn(v2), __float2half_rn(v3)));
    } else {
        *((float4*)(outf + (size_t)w * D) + lane) = make_float4(v0, v1, v2, v3);
    }
}

// ---------------- launch ----------------
extern "C" void kernel_launch(void* const* d_in, const int* in_sizes, int n_in,
                              void* d_out, int out_size)
{
    const float* x   = (const float*)d_in[0];
    const int*   ei  = (const int*)d_in[1];
    const float* W1l = (const float*)d_in[2];
    const float* b1  = (const float*)d_in[3];
    const float* W1r = (const float*)d_in[4];
    const float* W2l = (const float*)d_in[5];
    const float* b2  = (const float*)d_in[6];
    const float* W2r = (const float*)d_in[7];
    float* out = (float*)d_out;

    int N = in_sizes[0] / D;
    int E = in_sizes[1] / 2;
    const int* src = ei;
    const int* dst = ei + E;

    __half *hh, *yl, *z;
    u32 *B0, *B1, *B2, *B3;
    cudaGetSymbolAddress((void**)&hh, g_hh);
    cudaGetSymbolAddress((void**)&yl, g_yl);
    cudaGetSymbolAddress((void**)&z,  g_z);
    {
        u32* bb;
        cudaGetSymbolAddress((void**)&bb, g_B);
        B0 = bb; B1 = bb + 8192; B2 = bb + 16384; B3 = bb + 24576;
    }

    cudaFuncSetAttribute(k_gemm, cudaFuncAttributeMaxDynamicSharedMemorySize,
                         SM_U32_TOTAL * 4);

    static cudaStream_t sB = nullptr;
    static cudaEvent_t evFork = nullptr, evJoin = nullptr;
    if (!sB) {
        cudaStreamCreateWithFlags(&sB, cudaStreamNonBlocking);
        cudaEventCreateWithFlags(&evFork, cudaEventDisableTiming);
        cudaEventCreateWithFlags(&evJoin, cudaEventDisableTiming);
    }

    int e4 = (E + 3) / 4;
    int nb = (N + 1023) / 1024;
    int aggBlocks  = (N * 32 + 255) / 256;
    int gemmBlocks = (N + 127) / 128;

    // fork: CSR build on side stream
    cudaEventRecord(evFork, 0);
    cudaStreamWaitEvent(sB, evFork, 0);
    k_zero   <<<(N + 255) / 256, 256, 0, sB>>>(N);
    k_hist   <<<(e4 + 255) / 256, 256, 0, sB>>>(dst, e4);
    k_scanLB <<<nb, 1024, 0, sB>>>(N, E);
    k_scatter<<<(e4 + 255) / 256, 256, 0, sB>>>(src, dst, e4);
    cudaEventRecord(evJoin, sB);

    // main stream: weights + layer-1 GEMM (reads fp32 x directly)
    k_prepB<<<4, 256>>>(W1l, W1r, W2l, W2r);
    k_gemm <<<gemmBlocks, 256, SM_U32_TOTAL * 4>>>(
        x, nullptr, 1, B0, B1, b1, yl, z, N);

    // join, then agg/gemm/agg
    cudaStreamWaitEvent(0, evJoin, 0);
    k_aggf<<<aggBlocks, 256>>>(yl, z, hh, nullptr, 1, N);
    k_gemm<<<gemmBlocks, 256, SM_U32_TOTAL * 4>>>(
        nullptr, hh, 0, B2, B3, b2, yl, z, N);
    k_aggf<<<aggBlocks, 256>>>(yl, z, nullptr, out, 0, N);
}